// round 9
// baseline (speedup 1.0000x reference)
#include <cuda_runtime.h>
#include <cuda_bf16.h>
#include <cstdint>

typedef unsigned int u32;

#define D        512
#define BDIM     1024
#define C        200
#define NKEYS    50000
#define BM       64
#define BN       128
#define NTILES   391
#define NPAD     (NTILES * BN)
#define BTILES   (BDIM / BM)          // 16
#define NGROUPS  9                    // 144 CTAs = one wave
#define NSTAGES  4
#define NTHREADS 256
#define SB       72                   // B stage row stride (bf16)
#define SAQ      520                  // A panel row stride (bf16)
#define CP       201                  // csh row stride (floats)
#define SS       130                  // staging row stride (floats)

#define BS_BYTES (BN * SB * 2)                 // 18432
#define OFF_BS   0
#define OFF_AS   (NSTAGES * BS_BYTES)          // 73728
#define OFF_CSH  (OFF_AS + BM * SAQ * 2)       // 140288
#define OFF_LABS (OFF_CSH + BM * CP * 4)       // 191744
#define OFF_SIM  (OFF_LABS + BN * 4)           // 192256
#define SMEM_DYN (OFF_SIM + BM * SS * 4)       // 225536

// ---------------- device scratch ----------------
__device__ __align__(16) __nv_bfloat16 g_qbf[BDIM][D];
__device__ float g_qf[BDIM * D];
__device__ float g_tf[C * D];
__device__ __align__(16) __nv_bfloat16 g_kbf[NPAD][D];   // tail rows stay zero
__device__ int   g_lab[NPAD];
__device__ float g_part[NGROUPS * BDIM * C];

// ---------------- helpers ----------------
__device__ __forceinline__ u32 smem_u32(const void* p) {
    u32 a;
    asm("{ .reg .u64 t; cvta.to.shared.u64 t, %1; cvt.u32.u64 %0, t; }" : "=r"(a) : "l"(p));
    return a;
}

__device__ __forceinline__ void ldmx4(u32& r0, u32& r1, u32& r2, u32& r3, const void* p) {
    u32 addr = smem_u32(p);
    asm volatile("ldmatrix.sync.aligned.m8n8.x4.shared.b16 {%0,%1,%2,%3}, [%4];\n"
                 : "=r"(r0), "=r"(r1), "=r"(r2), "=r"(r3) : "r"(addr));
}

__device__ __forceinline__ void mma_bf16(float* d, const u32* a, const u32* b) {
    asm volatile(
        "mma.sync.aligned.m16n8k16.row.col.f32.bf16.bf16.f32 "
        "{%0,%1,%2,%3}, {%4,%5,%6,%7}, {%8,%9}, {%0,%1,%2,%3};\n"
        : "+f"(d[0]), "+f"(d[1]), "+f"(d[2]), "+f"(d[3])
        : "r"(a[0]), "r"(a[1]), "r"(a[2]), "r"(a[3]), "r"(b[0]), "r"(b[1]));
}

__device__ __forceinline__ void cp16(u32 dst, const void* src) {
    asm volatile("cp.async.cg.shared.global [%0], [%1], 16;" :: "r"(dst), "l"(src));
}
#define CP_COMMIT() asm volatile("cp.async.commit_group;" ::: "memory")
#define CP_WAIT3()  asm volatile("cp.async.wait_group 3;" ::: "memory")

// ---------------- prep ----------------
__device__ __forceinline__ float blk_sumsq(float4 x) {
    int t = threadIdx.x;
    float ss = x.x * x.x + x.y * x.y + x.z * x.z + x.w * x.w;
#pragma unroll
    for (int o = 16; o; o >>= 1) ss += __shfl_xor_sync(0xffffffffu, ss, o);
    __shared__ float ws[4];
    if ((t & 31) == 0) ws[t >> 5] = ss;
    __syncthreads();
    return ws[0] + ws[1] + ws[2] + ws[3];
}

__global__ void prep_q(const float* __restrict__ img) {
    int row = blockIdx.x, t = threadIdx.x;
    float4 x = ((const float4*)(img + row * D))[t];
    float inv = rsqrtf(blk_sumsq(x));
    float4 y = make_float4(x.x * inv, x.y * inv, x.z * inv, x.w * inv);
    ((float4*)(g_qf + row * D))[t] = y;
    __nv_bfloat162* dst = (__nv_bfloat162*)&g_qbf[row][0];
    dst[2 * t + 0] = __floats2bfloat162_rn(y.x, y.y);
    dst[2 * t + 1] = __floats2bfloat162_rn(y.z, y.w);
}

__global__ void prep_t(const float* __restrict__ txt) {
    int row = blockIdx.x, t = threadIdx.x;
    float4 x = ((const float4*)(txt + row * D))[t];
    float inv = rsqrtf(blk_sumsq(x));
    ((float4*)(g_tf + row * D))[t] = make_float4(x.x * inv, x.y * inv, x.z * inv, x.w * inv);
}

__global__ void prep_k(const float* __restrict__ keys, const int* __restrict__ labels) {
    int row = blockIdx.x, t = threadIdx.x;
    float4 x = ((const float4*)(keys + row * D))[t];
    float inv = rsqrtf(blk_sumsq(x));
    __nv_bfloat162* dst = (__nv_bfloat162*)&g_kbf[row][0];
    dst[2 * t + 0] = __floats2bfloat162_rn(x.x * inv, x.y * inv);
    dst[2 * t + 1] = __floats2bfloat162_rn(x.z * inv, x.w * inv);
    if (t == 0) {
        int l = labels[row];
        g_lab[row] = (l < 0) ? 0 : ((l >= C) ? C - 1 : l);
    }
}

// ---------------- main: 8 warps, 32x64 warp tiles, 2-way k-split ----------------
extern __shared__ unsigned char smraw[];

__global__ void __launch_bounds__(NTHREADS, 1) gemm_scatter() {
    __nv_bfloat16* As = (__nv_bfloat16*)(smraw + OFF_AS);
    float* csh  = (float*)(smraw + OFF_CSH);
    int*   labs = (int*)(smraw + OFF_LABS);
    float* ssim = (float*)(smraw + OFF_SIM);

    int tid = threadIdx.x;
    int lane = tid & 31, wid = tid >> 5;
    int grp = wid >> 2;                   // k-split group: 0 -> ks 0-1, 1 -> ks 2-3
    int w   = wid & 3;
    int wm  = w >> 1, wn = w & 1;         // 2x2 warps of 32x64 over 64x128
    int bt = blockIdx.x;
    int ng = blockIdx.y;

    for (int i = tid; i < BM * CP; i += NTHREADS) csh[i] = 0.f;

    // group 0 commit: A panel 64 x 512 bf16
    {
        u32 asb = smem_u32(As);
        const char* src = (const char*)&g_qbf[bt * BM][0];
#pragma unroll
        for (int k = 0; k < 16; k++) {
            int idx = tid + k * NTHREADS;     // 0..4095
            int r = idx >> 6, c = idx & 63;
            cp16(asb + (u32)(r * (SAQ * 2) + c * 16), src + r * (D * 2) + c * 16);
        }
        CP_COMMIT();
    }

    int nt = (NTILES - 1 - ng) / NGROUPS + 1;   // strided tiles: ng, ng+9, ...
    int nchunks = nt * 8;
    u32 bsb = smem_u32(smraw + OFF_BS);

    // prologue: chunks 0..2
    for (int p = 0; p < 3; p++) {
        int tloc = p >> 3, ch = p & 7;
        int n0 = (ng + tloc * NGROUPS) * BN;
        u32 sb = bsb + (u32)(p % NSTAGES) * BS_BYTES;
        const char* src = (const char*)&g_kbf[n0][0] + ch * 128;
#pragma unroll
        for (int k = 0; k < 4; k++) {
            int idx = tid + k * NTHREADS;     // 0..1023
            int r = idx >> 3, s = idx & 7;
            cp16(sb + (u32)(r * (SB * 2) + s * 16), src + r * (D * 2) + s * 16);
        }
        CP_COMMIT();
    }

    float acc[2][8][4];
#pragma unroll
    for (int mi = 0; mi < 2; mi++)
#pragma unroll
        for (int ni = 0; ni < 8; ni++)
#pragma unroll
            for (int e = 0; e < 4; e++) acc[mi][ni][e] = 0.f;

    for (int g = 0; g < nchunks; g++) {
        __syncthreads();                      // stage (g+3)%4 free to overwrite
        int pf = g + 3;
        if (pf < nchunks) {
            int tloc = pf >> 3, ch = pf & 7;
            int n0 = (ng + tloc * NGROUPS) * BN;
            u32 sb = bsb + (u32)(pf % NSTAGES) * BS_BYTES;
            const char* src = (const char*)&g_kbf[n0][0] + ch * 128;
#pragma unroll
            for (int k = 0; k < 4; k++) {
                int idx = tid + k * NTHREADS;
                int r = idx >> 3, s = idx & 7;
                cp16(sb + (u32)(r * (SB * 2) + s * 16), src + r * (D * 2) + s * 16);
            }
        }
        CP_COMMIT();
        CP_WAIT3();                           // chunk g (and A panel) resident
        __syncthreads();

        int ch = g & 7;
        if (ch == 0 && tid < BN) {
            int n0 = (ng + (g >> 3) * NGROUPS) * BN;
            labs[tid] = g_lab[n0 + tid];
        }

        __nv_bfloat16* Bst = (__nv_bfloat16*)(smraw + OFF_BS + (g % NSTAGES) * BS_BYTES);
#pragma unroll
        for (int ks = 0; ks < 2; ks++) {      // my group's half of k64
            int kk = (grp * 2 + ks) * 16;
            u32 afr[2][4];
#pragma unroll
            for (int mi = 0; mi < 2; mi++) {
                int rA = wm * 32 + mi * 16 + (lane & 7) + ((lane >> 3) & 1) * 8;
                int kA = ch * 64 + kk + ((lane >> 4) & 1) * 8;
                ldmx4(afr[mi][0], afr[mi][1], afr[mi][2], afr[mi][3], As + rA * SAQ + kA);
            }
            u32 bfr[8][2];
#pragma unroll
            for (int bg = 0; bg < 4; bg++) {
                int rB = wn * 64 + bg * 16 + (lane & 7) + ((lane >> 4) & 1) * 8;
                int kB = kk + ((lane >> 3) & 1) * 8;
                u32 r0, r1, r2, r3;
                ldmx4(r0, r1, r2, r3, Bst + rB * SB + kB);
                bfr[bg * 2 + 0][0] = r0; bfr[bg * 2 + 0][1] = r1;
                bfr[bg * 2 + 1][0] = r2; bfr[bg * 2 + 1][1] = r3;
            }
#pragma unroll
            for (int mi = 0; mi < 2; mi++)
#pragma unroll
                for (int ni = 0; ni < 8; ni++)
                    mma_bf16(acc[mi][ni], afr[mi], bfr[ni]);
        }

        if (ch == 7) {                        // tile done: cross-group reduce + scatter
            int n0 = (ng + (g >> 3) * NGROUPS) * BN;
            int rb = wm * 32 + (lane >> 2);
            if (grp == 0) {
#pragma unroll
                for (int mi = 0; mi < 2; mi++)
#pragma unroll
                    for (int ni = 0; ni < 8; ni++) {
                        int r = rb + mi * 16, c = wn * 64 + ni * 8 + 2 * (lane & 3);
                        *(float2*)&ssim[r * SS + c]       = make_float2(acc[mi][ni][0], acc[mi][ni][1]);
                        *(float2*)&ssim[(r + 8) * SS + c] = make_float2(acc[mi][ni][2], acc[mi][ni][3]);
                        acc[mi][ni][0] = acc[mi][ni][1] = acc[mi][ni][2] = acc[mi][ni][3] = 0.f;
                    }
            }
            __syncthreads();
            if (grp == 1) {
#pragma unroll
                for (int mi = 0; mi < 2; mi++)
#pragma unroll
                    for (int ni = 0; ni < 8; ni++) {
                        int r = rb + mi * 16, c = wn * 64 + ni * 8 + 2 * (lane & 3);
                        float2 a = *(float2*)&ssim[r * SS + c];
                        float2 b = *(float2*)&ssim[(r + 8) * SS + c];
                        *(float2*)&ssim[r * SS + c] =
                            make_float2(a.x + acc[mi][ni][0], a.y + acc[mi][ni][1]);
                        *(float2*)&ssim[(r + 8) * SS + c] =
                            make_float2(b.x + acc[mi][ni][2], b.y + acc[mi][ni][3]);
                        acc[mi][ni][0] = acc[mi][ni][1] = acc[mi][ni][2] = acc[mi][ni][3] = 0.f;
                    }
            }
            __syncthreads();
            int vc = NKEYS - n0; if (vc > BN) vc = BN;
#pragma unroll
            for (int j = 0; j < 32; j++) {
                int idx = tid + j * NTHREADS;     // 0..8191
                int r = idx >> 7, c = idx & 127;
                if (c < vc)
                    atomicAdd(&csh[r * CP + labs[c]], __expf(5.0f * ssim[r * SS + c]));
            }
        }
    }

    __syncthreads();
    float* dst = g_part + ((size_t)ng * BDIM + bt * BM) * C;
    for (int i = tid; i < BM * C; i += NTHREADS) {
        int r = i / C, c = i % C;
        dst[i] = csh[r * CP + c];
    }
}

// ---------------- z branch + combine partials ----------------
__global__ void __launch_bounds__(256) zcombine(float* __restrict__ out) {
    __shared__ float a2[64][17];
    __shared__ float b2[64][17];
    int tid = threadIdx.x;
    int tx = tid & 15, ty = tid >> 4;
    int rb = blockIdx.x * 64, cb = blockIdx.y * 64;

    float acc[4][4];
#pragma unroll
    for (int i = 0; i < 4; i++)
#pragma unroll
        for (int j = 0; j < 4; j++) acc[i][j] = 0.f;

    for (int k0 = 0; k0 < D; k0 += 16) {
        __syncthreads();
#pragma unroll
        for (int j = 0; j < 4; j++) {
            int idx = tid + j * 256;
            int r = idx >> 4, c = idx & 15;
            a2[r][c] = g_qf[(rb + r) * D + k0 + c];
            int cls = cb + r;
            b2[r][c] = (cls < C) ? g_tf[cls * D + k0 + c] : 0.f;
        }
        __syncthreads();
#pragma unroll
        for (int k = 0; k < 16; k++) {
            float av[4], bv[4];
#pragma unroll
            for (int i = 0; i < 4; i++) { av[i] = a2[ty * 4 + i][k]; bv[i] = b2[tx * 4 + i][k]; }
#pragma unroll
            for (int i = 0; i < 4; i++)
#pragma unroll
                for (int j = 0; j < 4; j++) acc[i][j] += av[i] * bv[j];
        }
    }

#pragma unroll
    for (int i = 0; i < 4; i++)
#pragma unroll
        for (int j = 0; j < 4; j++) {
            int r = rb + ty * 4 + i, c = cb + tx * 4 + j;
            if (c < C) {
                float s = 0.f;
#pragma unroll
                for (int gg = 0; gg < NGROUPS; gg++)
                    s += g_part[((size_t)gg * BDIM + r) * C + c];
                out[r * C + c] = 50.f * acc[i][j] + 0.5f * s;
            }
        }
}

// ---------------- launch ----------------
extern "C" void kernel_launch(void* const* d_in, const int* in_sizes, int n_in,
                              void* d_out, int out_size) {
    const float* img  = (const float*)d_in[0];
    const float* txt  = (const float*)d_in[1];
    const float* keys = (const float*)d_in[2];
    const int*   labs = (const int*)d_in[3];
    float* out = (float*)d_out;

    cudaFuncSetAttribute(gemm_scatter, cudaFuncAttributeMaxDynamicSharedMemorySize,
                         SMEM_DYN);

    prep_q<<<BDIM, 128>>>(img);
    prep_t<<<C, 128>>>(txt);
    prep_k<<<NKEYS, 128>>>(keys, labs);
    gemm_scatter<<<dim3(BTILES, NGROUPS), NTHREADS, SMEM_DYN>>>();
    zcombine<<<dim3(BDIM / 64, 4), 256>>>(out);
}

// round 10
// speedup vs baseline: 1.4315x; 1.4315x over previous
#include <cuda_runtime.h>
#include <cuda_bf16.h>
#include <cstdint>

typedef unsigned int u32;

#define D        512
#define BDIM     1024
#define C        200
#define NKEYS    50000
#define BM       32
#define BN       128
#define NTILES   391
#define NPAD     (NTILES * BN)
#define BTILES   (BDIM / BM)          // 32
#define NGROUPS  9                    // 32*9 = 288 CTAs = 2 waves of 2/SM
#define NSTAGES  2
#define NTHREADS 256
#define SB       72                   // B stage row stride (bf16)
#define SAQ      520                  // A panel row stride (bf16)
#define CP       200                  // csh row stride (floats)

#define BS_BYTES (BN * SB * 2)                 // 18432
#define OFF_BS   0
#define OFF_AS   (NSTAGES * BS_BYTES)          // 36864
#define OFF_CSH  (OFF_AS + BM * SAQ * 2)       // 70144
#define OFF_LABS (OFF_CSH + BM * CP * 4)       // 95744
#define SMEM_DYN (OFF_LABS + BN * 4)           // 96256  (x2 CTAs = 192.5K/SM)

// ---------------- device scratch ----------------
__device__ __align__(16) __nv_bfloat16 g_qbf[BDIM][D];
__device__ float g_qf[BDIM * D];
__device__ float g_tf[C * D];
__device__ __align__(16) __nv_bfloat16 g_kbf[NPAD][D];   // tail rows stay zero
__device__ int   g_lab[NPAD];
__device__ float g_part[NGROUPS * BDIM * C];

// ---------------- helpers ----------------
__device__ __forceinline__ u32 smem_u32(const void* p) {
    u32 a;
    asm("{ .reg .u64 t; cvta.to.shared.u64 t, %1; cvt.u32.u64 %0, t; }" : "=r"(a) : "l"(p));
    return a;
}

__device__ __forceinline__ void ldmx4(u32& r0, u32& r1, u32& r2, u32& r3, const void* p) {
    u32 addr = smem_u32(p);
    asm volatile("ldmatrix.sync.aligned.m8n8.x4.shared.b16 {%0,%1,%2,%3}, [%4];\n"
                 : "=r"(r0), "=r"(r1), "=r"(r2), "=r"(r3) : "r"(addr));
}

__device__ __forceinline__ void mma_bf16(float* d, const u32* a, const u32* b) {
    asm volatile(
        "mma.sync.aligned.m16n8k16.row.col.f32.bf16.bf16.f32 "
        "{%0,%1,%2,%3}, {%4,%5,%6,%7}, {%8,%9}, {%0,%1,%2,%3};\n"
        : "+f"(d[0]), "+f"(d[1]), "+f"(d[2]), "+f"(d[3])
        : "r"(a[0]), "r"(a[1]), "r"(a[2]), "r"(a[3]), "r"(b[0]), "r"(b[1]));
}

__device__ __forceinline__ void cp16(u32 dst, const void* src) {
    asm volatile("cp.async.cg.shared.global [%0], [%1], 16;" :: "r"(dst), "l"(src));
}
#define CP_COMMIT() asm volatile("cp.async.commit_group;" ::: "memory")
#define CP_WAIT1()  asm volatile("cp.async.wait_group 1;" ::: "memory")

// ---------------- prep ----------------
__device__ __forceinline__ float blk_sumsq(float4 x) {
    int t = threadIdx.x;
    float ss = x.x * x.x + x.y * x.y + x.z * x.z + x.w * x.w;
#pragma unroll
    for (int o = 16; o; o >>= 1) ss += __shfl_xor_sync(0xffffffffu, ss, o);
    __shared__ float ws[4];
    if ((t & 31) == 0) ws[t >> 5] = ss;
    __syncthreads();
    return ws[0] + ws[1] + ws[2] + ws[3];
}

__global__ void prep_q(const float* __restrict__ img) {
    int row = blockIdx.x, t = threadIdx.x;
    float4 x = ((const float4*)(img + row * D))[t];
    float inv = rsqrtf(blk_sumsq(x));
    float4 y = make_float4(x.x * inv, x.y * inv, x.z * inv, x.w * inv);
    ((float4*)(g_qf + row * D))[t] = y;
    __nv_bfloat162* dst = (__nv_bfloat162*)&g_qbf[row][0];
    dst[2 * t + 0] = __floats2bfloat162_rn(y.x, y.y);
    dst[2 * t + 1] = __floats2bfloat162_rn(y.z, y.w);
}

__global__ void prep_t(const float* __restrict__ txt) {
    int row = blockIdx.x, t = threadIdx.x;
    float4 x = ((const float4*)(txt + row * D))[t];
    float inv = rsqrtf(blk_sumsq(x));
    ((float4*)(g_tf + row * D))[t] = make_float4(x.x * inv, x.y * inv, x.z * inv, x.w * inv);
}

__global__ void prep_k(const float* __restrict__ keys, const int* __restrict__ labels) {
    int row = blockIdx.x, t = threadIdx.x;
    float4 x = ((const float4*)(keys + row * D))[t];
    float inv = rsqrtf(blk_sumsq(x));
    __nv_bfloat162* dst = (__nv_bfloat162*)&g_kbf[row][0];
    dst[2 * t + 0] = __floats2bfloat162_rn(x.x * inv, x.y * inv);
    dst[2 * t + 1] = __floats2bfloat162_rn(x.z * inv, x.w * inv);
    if (t == 0) {
        int l = labels[row];
        g_lab[row] = (l < 0) ? 0 : ((l >= C) ? C - 1 : l);
    }
}

// ---------------- main: 8 warps, 16x32 warp tiles, 2 CTAs/SM ----------------
extern __shared__ unsigned char smraw[];

__global__ void __launch_bounds__(NTHREADS, 2) gemm_scatter() {
    __nv_bfloat16* As = (__nv_bfloat16*)(smraw + OFF_AS);
    float* csh  = (float*)(smraw + OFF_CSH);
    int*   labs = (int*)(smraw + OFF_LABS);

    int tid = threadIdx.x;
    int lane = tid & 31, wid = tid >> 5;
    int wm = wid >> 2, wn = wid & 3;      // 2 x 4 warps, warp tile 16x32
    int bt = blockIdx.x;                  // 0..31
    int ng = blockIdx.y;                  // 0..8

    for (int i = tid; i < BM * CP; i += NTHREADS) csh[i] = 0.f;

    // group 0: A panel 32 x 512 bf16
    {
        u32 asb = smem_u32(As);
        const char* src = (const char*)&g_qbf[bt * BM][0];
#pragma unroll
        for (int k = 0; k < 8; k++) {
            int idx = tid + k * NTHREADS;     // 0..2047
            int r = idx >> 6, c = idx & 63;
            cp16(asb + (u32)(r * (SAQ * 2) + c * 16), src + r * (D * 2) + c * 16);
        }
        CP_COMMIT();
    }

    int nt = (NTILES - 1 - ng) / NGROUPS + 1;   // strided tiles: ng, ng+9, ...
    int nchunks = nt * 8;
    u32 bsb = smem_u32(smraw + OFF_BS);

    // prologue: chunk 0
    {
        int n0 = ng * BN;
        const char* src = (const char*)&g_kbf[n0][0];
#pragma unroll
        for (int k = 0; k < 4; k++) {
            int idx = tid + k * NTHREADS;     // 0..1023
            int r = idx >> 3, s = idx & 7;
            cp16(bsb + (u32)(r * (SB * 2) + s * 16), src + r * (D * 2) + s * 16);
        }
        CP_COMMIT();
    }

    float acc[4][4];
#pragma unroll
    for (int ni = 0; ni < 4; ni++)
#pragma unroll
        for (int e = 0; e < 4; e++) acc[ni][e] = 0.f;

    for (int g = 0; g < nchunks; g++) {
        __syncthreads();                      // stage (g+1)%2's prior reads done
        int pf = g + 1;
        if (pf < nchunks) {
            int tloc = pf >> 3, ch = pf & 7;
            int n0 = (ng + tloc * NGROUPS) * BN;
            u32 sb = bsb + (u32)(pf % NSTAGES) * BS_BYTES;
            const char* src = (const char*)&g_kbf[n0][0] + ch * 128;
#pragma unroll
            for (int k = 0; k < 4; k++) {
                int idx = tid + k * NTHREADS;
                int r = idx >> 3, s = idx & 7;
                cp16(sb + (u32)(r * (SB * 2) + s * 16), src + r * (D * 2) + s * 16);
            }
        }
        CP_COMMIT();
        CP_WAIT1();                           // chunk g (and A panel) resident
        __syncthreads();

        int ch = g & 7;
        if (ch == 0 && tid < BN) {
            int n0 = (ng + (g >> 3) * NGROUPS) * BN;
            labs[tid] = g_lab[n0 + tid];
        }

        __nv_bfloat16* Bst = (__nv_bfloat16*)(smraw + OFF_BS + (g % NSTAGES) * BS_BYTES);
#pragma unroll
        for (int ks = 0; ks < 4; ks++) {
            int kk = ks * 16;
            u32 afr[4];
            {
                int rA = wm * 16 + (lane & 7) + ((lane >> 3) & 1) * 8;
                int kA = ch * 64 + kk + ((lane >> 4) & 1) * 8;
                ldmx4(afr[0], afr[1], afr[2], afr[3], As + rA * SAQ + kA);
            }
            u32 bfr[4][2];
#pragma unroll
            for (int gg = 0; gg < 2; gg++) {
                int rB = wn * 32 + gg * 16 + (lane & 7) + ((lane >> 4) & 1) * 8;
                int kB = kk + ((lane >> 3) & 1) * 8;
                u32 r0, r1, r2, r3;
                ldmx4(r0, r1, r2, r3, Bst + rB * SB + kB);
                bfr[gg * 2 + 0][0] = r0; bfr[gg * 2 + 0][1] = r1;
                bfr[gg * 2 + 1][0] = r2; bfr[gg * 2 + 1][1] = r3;
            }
#pragma unroll
            for (int ni = 0; ni < 4; ni++)
                mma_bf16(acc[ni], afr, bfr[ni]);
        }

        if (ch == 7) {                        // tile done: exp + scatter
            int n0 = (ng + (g >> 3) * NGROUPS) * BN;
            int rb = wm * 16 + (lane >> 2);
#pragma unroll
            for (int ni = 0; ni < 4; ni++) {
                int cb = wn * 32 + ni * 8 + 2 * (lane & 3);
#pragma unroll
                for (int e = 0; e < 4; e++) {
                    int r = rb + ((e >= 2) ? 8 : 0);
                    int c = cb + (e & 1);
                    if (n0 + c < NKEYS) {
                        float v = __expf(5.0f * acc[ni][e]);
                        atomicAdd(&csh[r * CP + labs[c]], v);
                    }
                    acc[ni][e] = 0.f;
                }
            }
        }
    }

    __syncthreads();
    float* dst = g_part + ((size_t)ng * BDIM + bt * BM) * C;
    for (int i = tid; i < BM * C; i += NTHREADS)
        dst[i] = csh[i];                      // CP == C, direct copy
}

// ---------------- z branch + combine partials ----------------
__global__ void __launch_bounds__(256) zcombine(float* __restrict__ out) {
    __shared__ float a2[64][17];
    __shared__ float b2[64][17];
    int tid = threadIdx.x;
    int tx = tid & 15, ty = tid >> 4;
    int rb = blockIdx.x * 64, cb = blockIdx.y * 64;

    float acc[4][4];
#pragma unroll
    for (int i = 0; i < 4; i++)
#pragma unroll
        for (int j = 0; j < 4; j++) acc[i][j] = 0.f;

    for (int k0 = 0; k0 < D; k0 += 16) {
        __syncthreads();
#pragma unroll
        for (int j = 0; j < 4; j++) {
            int idx = tid + j * 256;
            int r = idx >> 4, c = idx & 15;
            a2[r][c] = g_qf[(rb + r) * D + k0 + c];
            int cls = cb + r;
            b2[r][c] = (cls < C) ? g_tf[cls * D + k0 + c] : 0.f;
        }
        __syncthreads();
#pragma unroll
        for (int k = 0; k < 16; k++) {
            float av[4], bv[4];
#pragma unroll
            for (int i = 0; i < 4; i++) { av[i] = a2[ty * 4 + i][k]; bv[i] = b2[tx * 4 + i][k]; }
#pragma unroll
            for (int i = 0; i < 4; i++)
#pragma unroll
                for (int j = 0; j < 4; j++) acc[i][j] += av[i] * bv[j];
        }
    }

#pragma unroll
    for (int i = 0; i < 4; i++)
#pragma unroll
        for (int j = 0; j < 4; j++) {
            int r = rb + ty * 4 + i, c = cb + tx * 4 + j;
            if (c < C) {
                float s = 0.f;
#pragma unroll
                for (int gg = 0; gg < NGROUPS; gg++)
                    s += g_part[((size_t)gg * BDIM + r) * C + c];
                out[r * C + c] = 50.f * acc[i][j] + 0.5f * s;
            }
        }
}

// ---------------- launch ----------------
extern "C" void kernel_launch(void* const* d_in, const int* in_sizes, int n_in,
                              void* d_out, int out_size) {
    const float* img  = (const float*)d_in[0];
    const float* txt  = (const float*)d_in[1];
    const float* keys = (const float*)d_in[2];
    const int*   labs = (const int*)d_in[3];
    float* out = (float*)d_out;

    cudaFuncSetAttribute(gemm_scatter, cudaFuncAttributeMaxDynamicSharedMemorySize,
                         SMEM_DYN);

    prep_q<<<BDIM, 128>>>(img);
    prep_t<<<C, 128>>>(txt);
    prep_k<<<NKEYS, 128>>>(keys, labs);
    gemm_scatter<<<dim3(BTILES, NGROUPS), NTHREADS, SMEM_DYN>>>();
    zcombine<<<dim3(BDIM / 64, 4), 256>>>(out);
}

// round 12
// speedup vs baseline: 2.2353x; 1.5615x over previous
#include <cuda_runtime.h>
#include <cuda_bf16.h>
#include <cstdint>
#include <cstring>

typedef unsigned int u32;

#define D        512
#define KT       32                  // D/16 k-tiles
#define BDIM     1024
#define C        200
#define NKEYS    50000
#define BM       128
#define BN       128
#define NTILES   391
#define NPAD     (NTILES * BN)       // 50048
#define NT16     (NPAD / 16)         // 3128
#define BTILES   (BDIM / BM)         // 8
#define NGROUPS  18                  // 8*18 = 144 CTAs = one wave
#define NTHREADS 512
#define CP       201                 // csh row stride (floats, odd)
#define SMEM_DYN (BM * CP * 4)       // 102912

// ---------------- device scratch (fragment-major layouts) ----------------
__device__ __align__(16) uint4 g_qfrag[BDIM / 16][KT][32];
__device__ __align__(16) uint4 g_kfrag[NT16][KT][32];    // tail tiles stay zero
__device__ float g_qf[BDIM * D];
__device__ float g_tf[C * D];
__device__ int   g_lab[NPAD];
__device__ float g_part[NGROUPS * BDIM * C];

// ---------------- helpers ----------------
__device__ __forceinline__ u32 bf2u(__nv_bfloat162 v) {
    u32 r;
    memcpy(&r, &v, 4);
    return r;
}

__device__ __forceinline__ void mma_bf16(float* d, const u32* a, const u32* b) {
    asm volatile(
        "mma.sync.aligned.m16n8k16.row.col.f32.bf16.bf16.f32 "
        "{%0,%1,%2,%3}, {%4,%5,%6,%7}, {%8,%9}, {%0,%1,%2,%3};\n"
        : "+f"(d[0]), "+f"(d[1]), "+f"(d[2]), "+f"(d[3])
        : "r"(a[0]), "r"(a[1]), "r"(a[2]), "r"(a[3]), "r"(b[0]), "r"(b[1]));
}

// ---------------- prep: normalize + write fragment-major tiles ----------------
// one block = 16 rows = one 16-row tile strip; 512 threads (16 warps)
__global__ void __launch_bounds__(512) prep_q(const float* __restrict__ img) {
    __shared__ u32 sh[16][260];           // [row][k/2], stride 260 = conflict-free gather
    int t = threadIdx.x, w = t >> 5, l = t & 31;
    int row = blockIdx.x * 16 + w;
    const float4* src = (const float4*)(img + row * D);
    float4 v[4]; float ss = 0.f;
#pragma unroll
    for (int j = 0; j < 4; j++) {
        v[j] = src[j * 32 + l];
        ss += v[j].x * v[j].x + v[j].y * v[j].y + v[j].z * v[j].z + v[j].w * v[j].w;
    }
#pragma unroll
    for (int o = 16; o; o >>= 1) ss += __shfl_xor_sync(0xffffffffu, ss, o);
    float inv = rsqrtf(ss);
    float4* qf = (float4*)(g_qf + row * D);
#pragma unroll
    for (int j = 0; j < 4; j++) {
        float4 y = make_float4(v[j].x * inv, v[j].y * inv, v[j].z * inv, v[j].w * inv);
        qf[j * 32 + l] = y;
        int col = (j * 32 + l) * 2;
        sh[w][col]     = bf2u(__floats2bfloat162_rn(y.x, y.y));
        sh[w][col + 1] = bf2u(__floats2bfloat162_rn(y.z, y.w));
    }
    __syncthreads();
#pragma unroll
    for (int s = t; s < 1024; s += 512) {
        int kt = s >> 5, ln = s & 31;
        int ka = kt * 8 + (ln & 3), kb = ka + 4, r0 = ln >> 2;
        uint4 f;
        f.x = sh[r0][ka]; f.y = sh[r0 + 8][ka]; f.z = sh[r0][kb]; f.w = sh[r0 + 8][kb];
        g_qfrag[blockIdx.x][kt][ln] = f;
    }
}

__global__ void __launch_bounds__(512) prep_k(const float* __restrict__ keys,
                                              const int* __restrict__ labels) {
    __shared__ u32 sh[16][260];
    int t = threadIdx.x, w = t >> 5, l = t & 31;
    int row = blockIdx.x * 16 + w;
    const float4* src = (const float4*)(keys + row * D);
    float4 v[4]; float ss = 0.f;
#pragma unroll
    for (int j = 0; j < 4; j++) {
        v[j] = src[j * 32 + l];
        ss += v[j].x * v[j].x + v[j].y * v[j].y + v[j].z * v[j].z + v[j].w * v[j].w;
    }
#pragma unroll
    for (int o = 16; o; o >>= 1) ss += __shfl_xor_sync(0xffffffffu, ss, o);
    float inv = rsqrtf(ss);
#pragma unroll
    for (int j = 0; j < 4; j++) {
        int col = (j * 32 + l) * 2;
        sh[w][col]     = bf2u(__floats2bfloat162_rn(v[j].x * inv, v[j].y * inv));
        sh[w][col + 1] = bf2u(__floats2bfloat162_rn(v[j].z * inv, v[j].w * inv));
    }
    if (w == 0 && l < 16) {
        int rr = blockIdx.x * 16 + l;
        int lb = labels[rr];
        g_lab[rr] = (lb < 0) ? 0 : ((lb >= C) ? C - 1 : lb);
    }
    __syncthreads();
#pragma unroll
    for (int s = t; s < 1024; s += 512) {
        int kt = s >> 5, ln = s & 31;
        int ka = kt * 8 + (ln & 3), kb = ka + 4, n0 = ln >> 2;
        uint4 f;
        f.x = sh[n0][ka]; f.y = sh[n0][kb]; f.z = sh[n0 + 8][ka]; f.w = sh[n0 + 8][kb];
        g_kfrag[blockIdx.x][kt][ln] = f;
    }
}

// ---------------- main: barrier-free direct-LDG fragment GEMM + scatter ----------------
extern __shared__ float csh[];

__global__ void __launch_bounds__(NTHREADS, 1) gemm_scatter() {
    int tid = threadIdx.x;
    int lane = tid & 31, wid = tid >> 5;
    int wm = wid >> 2, wn = wid & 3;          // 4x4 warps, warp tile 32x32
    int bt = blockIdx.x;                      // 0..7
    int ng = blockIdx.y;                      // 0..17

    for (int i = tid; i < BM * CP; i += NTHREADS) csh[i] = 0.f;
    __syncthreads();

    int mt0 = bt * 8 + wm * 2;
    const uint4* A0 = &g_qfrag[mt0][0][lane];
    const uint4* A1 = &g_qfrag[mt0 + 1][0][lane];

    int nt = (NTILES - 1 - ng) / NGROUPS + 1;     // strided tiles: ng, ng+18, ...
    for (int tl = 0; tl < nt; tl++) {
        int ntile = ng + tl * NGROUPS;
        int n0 = ntile * BN;
        const uint4* B0 = &g_kfrag[ntile * 8 + wn * 2][0][lane];
        const uint4* B1 = B0 + KT * 32;

        float acc[2][4][4];
#pragma unroll
        for (int mi = 0; mi < 2; mi++)
#pragma unroll
            for (int ni = 0; ni < 4; ni++)
#pragma unroll
                for (int e = 0; e < 4; e++) acc[mi][ni][e] = 0.f;

#pragma unroll 4
        for (int kt = 0; kt < KT; kt++) {
            uint4 av0 = A0[kt * 32];
            uint4 av1 = A1[kt * 32];
            uint4 bv0 = B0[kt * 32];
            uint4 bv1 = B1[kt * 32];
            u32 Ar0[4] = {av0.x, av0.y, av0.z, av0.w};
            u32 Ar1[4] = {av1.x, av1.y, av1.z, av1.w};
            u32 Bp[4][2] = {{bv0.x, bv0.y}, {bv0.z, bv0.w},
                            {bv1.x, bv1.y}, {bv1.z, bv1.w}};
#pragma unroll
            for (int ni = 0; ni < 4; ni++) {
                mma_bf16(acc[0][ni], Ar0, Bp[ni]);
                mma_bf16(acc[1][ni], Ar1, Bp[ni]);
            }
        }

        // epilogue: exp + label scatter into csh (atomics; no sync needed)
#pragma unroll
        for (int mi = 0; mi < 2; mi++) {
#pragma unroll
            for (int ni = 0; ni < 4; ni++) {
                int rb = wm * 32 + mi * 16 + (lane >> 2);
                int cb = wn * 32 + ni * 8 + 2 * (lane & 3);
#pragma unroll
                for (int e = 0; e < 4; e++) {
                    int r = rb + ((e >= 2) ? 8 : 0);
                    int c = cb + (e & 1);
                    int n = n0 + c;
                    if (n < NKEYS) {
                        float v = __expf(5.0f * acc[mi][ni][e]);
                        atomicAdd(&csh[r * CP + g_lab[n]], v);
                    }
                }
            }
        }
    }

    __syncthreads();
    float* dst = g_part + ((size_t)ng * BDIM + bt * BM) * C;
    for (int i = tid; i < BM * C; i += NTHREADS) {
        int r = i / C, c = i % C;
        dst[i] = csh[r * CP + c];
    }
}

// ---------------- z branch + combine partials ----------------
__global__ void __launch_bounds__(256) zcombine(float* __restrict__ out) {
    __shared__ float a2[64][17];
    __shared__ float b2[64][17];
    int tid = threadIdx.x;
    int tx = tid & 15, ty = tid >> 4;
    int rb = blockIdx.x * 64, cb = blockIdx.y * 64;

    float acc[4][4];
#pragma unroll
    for (int i = 0; i < 4; i++)
#pragma unroll
        for (int j = 0; j < 4; j++) acc[i][j] = 0.f;

    for (int k0 = 0; k0 < D; k0 += 16) {
        __syncthreads();
#pragma unroll
        for (int j = 0; j < 4; j++) {
            int idx = tid + j * 256;
            int r = idx >> 4, c = idx & 15;
            a2[r][c] = g_qf[(rb + r) * D + k0 + c];
            int cls = cb + r;
            b2[r][c] = (cls < C) ? g_tf[cls * D + k0 + c] : 0.f;
        }
        __syncthreads();
#pragma unroll
        for (int k = 0; k < 16; k++) {
            float av[4], bv[4];
#pragma unroll
            for (int i = 0; i < 4; i++) { av[i] = a2[ty * 4 + i][k]; bv[i] = b2[tx * 4 + i][k]; }
#pragma unroll
            for (int i = 0; i < 4; i++)
#pragma unroll
                for (int j = 0; j < 4; j++) acc[i][j] += av[i] * bv[j];
        }
    }

#pragma unroll
    for (int i = 0; i < 4; i++)
#pragma unroll
        for (int j = 0; j < 4; j++) {
            int r = rb + ty * 4 + i, c = cb + tx * 4 + j;
            if (c < C) {
                float s = 0.f;
#pragma unroll
                for (int gg = 0; gg < NGROUPS; gg++)
                    s += g_part[((size_t)gg * BDIM + r) * C + c];
                out[r * C + c] = 50.f * acc[i][j] + 0.5f * s;
            }
        }
}

__global__ void prep_t(const float* __restrict__ txt) {
    int row = blockIdx.x, t = threadIdx.x;
    float4 x = ((const float4*)(txt + row * D))[t];
    float ss = x.x * x.x + x.y * x.y + x.z * x.z + x.w * x.w;
#pragma unroll
    for (int o = 16; o; o >>= 1) ss += __shfl_xor_sync(0xffffffffu, ss, o);
    __shared__ float ws[4];
    if ((t & 31) == 0) ws[t >> 5] = ss;
    __syncthreads();
    float inv = rsqrtf(ws[0] + ws[1] + ws[2] + ws[3]);
    ((float4*)(g_tf + row * D))[t] = make_float4(x.x * inv, x.y * inv, x.z * inv, x.w * inv);
}

// ---------------- launch ----------------
extern "C" void kernel_launch(void* const* d_in, const int* in_sizes, int n_in,
                              void* d_out, int out_size) {
    const float* img  = (const float*)d_in[0];
    const float* txt  = (const float*)d_in[1];
    const float* keys = (const float*)d_in[2];
    const int*   labs = (const int*)d_in[3];
    float* out = (float*)d_out;

    cudaFuncSetAttribute(gemm_scatter, cudaFuncAttributeMaxDynamicSharedMemorySize,
                         SMEM_DYN);

    prep_q<<<BDIM / 16, 512>>>(img);
    prep_t<<<C, 128>>>(txt);
    prep_k<<<NKEYS / 16, 512>>>(keys, labs);
    gemm_scatter<<<dim3(BTILES, NGROUPS), NTHREADS, SMEM_DYN>>>();
    zcombine<<<dim3(BDIM / 64, 4), 256>>>(out);
}

// round 13
// speedup vs baseline: 2.3593x; 1.0555x over previous
#include <cuda_runtime.h>
#include <cuda_bf16.h>
#include <cstdint>
#include <cstring>

typedef unsigned int u32;

#define D        512
#define KT       32                  // D/16 k-tiles
#define BDIM     1024
#define C        200
#define NKEYS    50000
#define BM       128
#define BN       128
#define NTILES   391
#define NPAD     (NTILES * BN)       // 50048
#define NT16     (NPAD / 16)         // 3128
#define BTILES   (BDIM / BM)         // 8
#define NGROUPS  18                  // 8*18 = 144 CTAs = one wave
#define NTHREADS 512
#define CP       201                 // csh row stride (floats, odd)
#define SMEM_DYN (BM * CP * 4)       // 102912

// ---------------- device scratch (fragment-major layouts) ----------------
__device__ __align__(16) uint4 g_qfrag[BDIM / 16][KT][32];
__device__ __align__(16) uint4 g_kfrag[NT16][KT][32];    // tail tiles stay zero
__device__ float g_qf[BDIM * D];
__device__ float g_tf[C * D];
__device__ int   g_lab[NPAD];
__device__ float g_part[NGROUPS * BDIM * C];

// ---------------- helpers ----------------
__device__ __forceinline__ u32 bf2u(__nv_bfloat162 v) {
    u32 r;
    memcpy(&r, &v, 4);
    return r;
}

__device__ __forceinline__ void mma_bf16(float* d, const u32* a, const u32* b) {
    asm volatile(
        "mma.sync.aligned.m16n8k16.row.col.f32.bf16.bf16.f32 "
        "{%0,%1,%2,%3}, {%4,%5,%6,%7}, {%8,%9}, {%0,%1,%2,%3};\n"
        : "+f"(d[0]), "+f"(d[1]), "+f"(d[2]), "+f"(d[3])
        : "r"(a[0]), "r"(a[1]), "r"(a[2]), "r"(a[3]), "r"(b[0]), "r"(b[1]));
}

// A: keep resident in L1 across the whole kernel (evict_last)
__device__ __forceinline__ uint4 ldg_keep(const uint4* p) {
    uint4 v;
    asm volatile("ld.global.nc.L1::evict_last.v4.u32 {%0,%1,%2,%3}, [%4];"
                 : "=r"(v.x), "=r"(v.y), "=r"(v.z), "=r"(v.w) : "l"(p));
    return v;
}
// B: streaming, evict first so it never displaces A
__device__ __forceinline__ uint4 ldg_stream(const uint4* p) {
    uint4 v;
    asm volatile("ld.global.nc.L1::evict_first.v4.u32 {%0,%1,%2,%3}, [%4];"
                 : "=r"(v.x), "=r"(v.y), "=r"(v.z), "=r"(v.w) : "l"(p));
    return v;
}

// ---------------- prep: normalize + write fragment-major tiles ----------------
__global__ void __launch_bounds__(512) prep_q(const float* __restrict__ img) {
    __shared__ u32 sh[16][260];
    int t = threadIdx.x, w = t >> 5, l = t & 31;
    int row = blockIdx.x * 16 + w;
    const float4* src = (const float4*)(img + row * D);
    float4 v[4]; float ss = 0.f;
#pragma unroll
    for (int j = 0; j < 4; j++) {
        v[j] = src[j * 32 + l];
        ss += v[j].x * v[j].x + v[j].y * v[j].y + v[j].z * v[j].z + v[j].w * v[j].w;
    }
#pragma unroll
    for (int o = 16; o; o >>= 1) ss += __shfl_xor_sync(0xffffffffu, ss, o);
    float inv = rsqrtf(ss);
    float4* qf = (float4*)(g_qf + row * D);
#pragma unroll
    for (int j = 0; j < 4; j++) {
        float4 y = make_float4(v[j].x * inv, v[j].y * inv, v[j].z * inv, v[j].w * inv);
        qf[j * 32 + l] = y;
        int col = (j * 32 + l) * 2;
        sh[w][col]     = bf2u(__floats2bfloat162_rn(y.x, y.y));
        sh[w][col + 1] = bf2u(__floats2bfloat162_rn(y.z, y.w));
    }
    __syncthreads();
#pragma unroll
    for (int s = t; s < 1024; s += 512) {
        int kt = s >> 5, ln = s & 31;
        int ka = kt * 8 + (ln & 3), kb = ka + 4, r0 = ln >> 2;
        uint4 f;
        f.x = sh[r0][ka]; f.y = sh[r0 + 8][ka]; f.z = sh[r0][kb]; f.w = sh[r0 + 8][kb];
        g_qfrag[blockIdx.x][kt][ln] = f;
    }
}

__global__ void __launch_bounds__(512) prep_k(const float* __restrict__ keys,
                                              const int* __restrict__ labels) {
    __shared__ u32 sh[16][260];
    int t = threadIdx.x, w = t >> 5, l = t & 31;
    int row = blockIdx.x * 16 + w;
    const float4* src = (const float4*)(keys + row * D);
    float4 v[4]; float ss = 0.f;
#pragma unroll
    for (int j = 0; j < 4; j++) {
        v[j] = src[j * 32 + l];
        ss += v[j].x * v[j].x + v[j].y * v[j].y + v[j].z * v[j].z + v[j].w * v[j].w;
    }
#pragma unroll
    for (int o = 16; o; o >>= 1) ss += __shfl_xor_sync(0xffffffffu, ss, o);
    float inv = rsqrtf(ss);
#pragma unroll
    for (int j = 0; j < 4; j++) {
        int col = (j * 32 + l) * 2;
        sh[w][col]     = bf2u(__floats2bfloat162_rn(v[j].x * inv, v[j].y * inv));
        sh[w][col + 1] = bf2u(__floats2bfloat162_rn(v[j].z * inv, v[j].w * inv));
    }
    if (w == 0 && l < 16) {
        int rr = blockIdx.x * 16 + l;
        int lb = labels[rr];
        g_lab[rr] = (lb < 0) ? 0 : ((lb >= C) ? C - 1 : lb);
    }
    __syncthreads();
#pragma unroll
    for (int s = t; s < 1024; s += 512) {
        int kt = s >> 5, ln = s & 31;
        int ka = kt * 8 + (ln & 3), kb = ka + 4, n0 = ln >> 2;
        uint4 f;
        f.x = sh[n0][ka]; f.y = sh[n0][kb]; f.z = sh[n0 + 8][ka]; f.w = sh[n0 + 8][kb];
        g_kfrag[blockIdx.x][kt][ln] = f;
    }
}

// ---------------- main: barrier-free direct-LDG fragment GEMM + scatter ----------------
extern __shared__ float csh[];

__global__ void __launch_bounds__(NTHREADS, 1) gemm_scatter() {
    int tid = threadIdx.x;
    int lane = tid & 31, wid = tid >> 5;
    int wm = wid >> 2, wn = wid & 3;          // 4x4 warps, warp tile 32x32
    int bt = blockIdx.x;                      // 0..7
    int ng = blockIdx.y;                      // 0..17

    for (int i = tid; i < BM * CP; i += NTHREADS) csh[i] = 0.f;
    __syncthreads();

    int mt0 = bt * 8 + wm * 2;
    const uint4* A0 = &g_qfrag[mt0][0][lane];
    const uint4* A1 = &g_qfrag[mt0 + 1][0][lane];

    int nt = (NTILES - 1 - ng) / NGROUPS + 1;     // strided tiles: ng, ng+18, ...
    for (int tl = 0; tl < nt; tl++) {
        int ntile = ng + tl * NGROUPS;
        int n0 = ntile * BN;
        const uint4* B0 = &g_kfrag[ntile * 8 + wn * 2][0][lane];
        const uint4* B1 = B0 + KT * 32;

        float acc[2][4][4];
#pragma unroll
        for (int mi = 0; mi < 2; mi++)
#pragma unroll
            for (int ni = 0; ni < 4; ni++)
#pragma unroll
                for (int e = 0; e < 4; e++) acc[mi][ni][e] = 0.f;

#pragma unroll 8
        for (int kt = 0; kt < KT; kt++) {
            uint4 av0 = ldg_keep(A0 + kt * 32);
            uint4 av1 = ldg_keep(A1 + kt * 32);
            uint4 bv0 = ldg_stream(B0 + kt * 32);
            uint4 bv1 = ldg_stream(B1 + kt * 32);
            u32 Ar0[4] = {av0.x, av0.y, av0.z, av0.w};
            u32 Ar1[4] = {av1.x, av1.y, av1.z, av1.w};
            u32 Bp[4][2] = {{bv0.x, bv0.y}, {bv0.z, bv0.w},
                            {bv1.x, bv1.y}, {bv1.z, bv1.w}};
#pragma unroll
            for (int ni = 0; ni < 4; ni++) {
                mma_bf16(acc[0][ni], Ar0, Bp[ni]);
                mma_bf16(acc[1][ni], Ar1, Bp[ni]);
            }
        }

        // epilogue: exp + label scatter into csh (atomics; no sync needed)
        if (n0 + BN <= NKEYS) {                   // full tile: no guards
#pragma unroll
            for (int mi = 0; mi < 2; mi++) {
#pragma unroll
                for (int ni = 0; ni < 4; ni++) {
                    int rb = wm * 32 + mi * 16 + (lane >> 2);
                    int cb = wn * 32 + ni * 8 + 2 * (lane & 3);
#pragma unroll
                    for (int e = 0; e < 4; e++) {
                        int r = rb + ((e >= 2) ? 8 : 0);
                        int c = cb + (e & 1);
                        float v = __expf(5.0f * acc[mi][ni][e]);
                        atomicAdd(&csh[r * CP + __ldg(&g_lab[n0 + c])], v);
                    }
                }
            }
        } else {                                  // tail tile (only ntile==390)
#pragma unroll
            for (int mi = 0; mi < 2; mi++) {
#pragma unroll
                for (int ni = 0; ni < 4; ni++) {
                    int rb = wm * 32 + mi * 16 + (lane >> 2);
                    int cb = wn * 32 + ni * 8 + 2 * (lane & 3);
#pragma unroll
                    for (int e = 0; e < 4; e++) {
                        int r = rb + ((e >= 2) ? 8 : 0);
                        int c = cb + (e & 1);
                        int n = n0 + c;
                        if (n < NKEYS) {
                            float v = __expf(5.0f * acc[mi][ni][e]);
                            atomicAdd(&csh[r * CP + __ldg(&g_lab[n])], v);
                        }
                    }
                }
            }
        }
    }

    __syncthreads();
    float* dst = g_part + ((size_t)ng * BDIM + bt * BM) * C;
    for (int i = tid; i < BM * C; i += NTHREADS) {
        int r = i / C, c = i % C;
        dst[i] = csh[r * CP + c];
    }
}

// ---------------- z branch + combine partials ----------------
__global__ void __launch_bounds__(256) zcombine(float* __restrict__ out) {
    __shared__ float a2[64][17];
    __shared__ float b2[64][17];
    int tid = threadIdx.x;
    int tx = tid & 15, ty = tid >> 4;
    int rb = blockIdx.x * 64, cb = blockIdx.y * 64;

    float acc[4][4];
#pragma unroll
    for (int i = 0; i < 4; i++)
#pragma unroll
        for (int j = 0; j < 4; j++) acc[i][j] = 0.f;

    for (int k0 = 0; k0 < D; k0 += 16) {
        __syncthreads();
#pragma unroll
        for (int j = 0; j < 4; j++) {
            int idx = tid + j * 256;
            int r = idx >> 4, c = idx & 15;
            a2[r][c] = g_qf[(rb + r) * D + k0 + c];
            int cls = cb + r;
            b2[r][c] = (cls < C) ? g_tf[cls * D + k0 + c] : 0.f;
        }
        __syncthreads();
#pragma unroll
        for (int k = 0; k < 16; k++) {
            float av[4], bv[4];
#pragma unroll
            for (int i = 0; i < 4; i++) { av[i] = a2[ty * 4 + i][k]; bv[i] = b2[tx * 4 + i][k]; }
#pragma unroll
            for (int i = 0; i < 4; i++)
#pragma unroll
                for (int j = 0; j < 4; j++) acc[i][j] += av[i] * bv[j];
        }
    }

#pragma unroll
    for (int i = 0; i < 4; i++)
#pragma unroll
        for (int j = 0; j < 4; j++) {
            int r = rb + ty * 4 + i, c = cb + tx * 4 + j;
            if (c < C) {
                float s = 0.f;
#pragma unroll
                for (int gg = 0; gg < NGROUPS; gg++)
                    s += g_part[((size_t)gg * BDIM + r) * C + c];
                out[r * C + c] = 50.f * acc[i][j] + 0.5f * s;
            }
        }
}

__global__ void prep_t(const float* __restrict__ txt) {
    int row = blockIdx.x, t = threadIdx.x;
    float4 x = ((const float4*)(txt + row * D))[t];
    float ss = x.x * x.x + x.y * x.y + x.z * x.z + x.w * x.w;
#pragma unroll
    for (int o = 16; o; o >>= 1) ss += __shfl_xor_sync(0xffffffffu, ss, o);
    __shared__ float ws[4];
    if ((t & 31) == 0) ws[t >> 5] = ss;
    __syncthreads();
    float inv = rsqrtf(ws[0] + ws[1] + ws[2] + ws[3]);
    ((float4*)(g_tf + row * D))[t] = make_float4(x.x * inv, x.y * inv, x.z * inv, x.w * inv);
}

// ---------------- launch ----------------
extern "C" void kernel_launch(void* const* d_in, const int* in_sizes, int n_in,
                              void* d_out, int out_size) {
    const float* img  = (const float*)d_in[0];
    const float* txt  = (const float*)d_in[1];
    const float* keys = (const float*)d_in[2];
    const int*   labs = (const int*)d_in[3];
    float* out = (float*)d_out;

    cudaFuncSetAttribute(gemm_scatter, cudaFuncAttributeMaxDynamicSharedMemorySize,
                         SMEM_DYN);

    prep_q<<<BDIM / 16, 512>>>(img);
    prep_t<<<C, 128>>>(txt);
    prep_k<<<NKEYS / 16, 512>>>(keys, labs);
    gemm_scatter<<<dim3(BTILES, NGROUPS), NTHREADS, SMEM_DYN>>>();
    zcombine<<<dim3(BDIM / 64, 4), 256>>>(out);
}